// round 3
// baseline (speedup 1.0000x reference)
#include <cuda_runtime.h>

#define T_    512
#define DF    64
#define NPAIR 60
#define NDIAG 1023
#define BIGV  1e10f
#define RING_K 1032
#define SMEM_DYN (15 * RING_K * 8 + 64)

static __device__ float g_Dd[(size_t)NPAIR * NDIAG * T_];   // anti-diagonal cost matrices
static __device__ float g_raw[NPAIR];
static __device__ float g_Gp[64 * 48 * 48];                 // gram partials per k-chunk

__device__ __forceinline__ float fex2(float x) { float y; asm("ex2.approx.f32 %0, %1;" : "=f"(y) : "f"(x)); return y; }
__device__ __forceinline__ float flg2(float x) { float y; asm("lg2.approx.f32 %0, %1;" : "=f"(y) : "f"(x)); return y; }

// ---------------------------------------------------------------------------
// Kernel A: squared-Euclidean cost tiles -> anti-diagonal layout g_Dd[p][i+j][i]
// ---------------------------------------------------------------------------
__global__ __launch_bounds__(256) void cost_kernel(const float* __restrict__ data,
                                                   const int* __restrict__ lens) {
    int p = blockIdx.z;
    int w = p / 15, jj = p % 15 + 1;
    int arow = w * 16, brow = arow + jj;
    int la = lens[arow], lb = lens[brow];
    int i0 = blockIdx.y * 64, j0 = blockIdx.x * 64;
    if (i0 >= la || j0 >= lb) return;

    __shared__ float As[64][68];
    __shared__ float Bs[64][68];
    __shared__ float Ct[64][66];
    __shared__ float a2s[64], b2s[64];

    int tid = threadIdx.x;
    const float* Ap = data + (size_t)arow * T_ * DF;
    const float* Bp = data + (size_t)brow * T_ * DF;
#pragma unroll
    for (int it = 0; it < 4; ++it) {
        int f = tid + it * 256;
        int r = f >> 4, q = f & 15;
        float4 va = *(const float4*)(Ap + (size_t)(i0 + r) * DF + q * 4);
        float4 vb = *(const float4*)(Bp + (size_t)(j0 + r) * DF + q * 4);
        As[q * 4 + 0][r] = va.x; As[q * 4 + 1][r] = va.y; As[q * 4 + 2][r] = va.z; As[q * 4 + 3][r] = va.w;
        Bs[q * 4 + 0][r] = vb.x; Bs[q * 4 + 1][r] = vb.y; Bs[q * 4 + 2][r] = vb.z; Bs[q * 4 + 3][r] = vb.w;
    }
    __syncthreads();

    if (tid < 64) {
        float s = 0.f;
#pragma unroll
        for (int k = 0; k < 64; ++k) { float v = As[k][tid]; s = fmaf(v, v, s); }
        a2s[tid] = s;
    } else if (tid < 128) {
        int r = tid - 64; float s = 0.f;
#pragma unroll
        for (int k = 0; k < 64; ++k) { float v = Bs[k][r]; s = fmaf(v, v, s); }
        b2s[r] = s;
    }

    int tx = tid & 15, ty = tid >> 4;
    int ib = ty * 4, jb = tx * 4;
    float acc[4][4] = {};
#pragma unroll 16
    for (int k = 0; k < 64; ++k) {
        float4 av = *(const float4*)&As[k][ib];
        float4 bv = *(const float4*)&Bs[k][jb];
        acc[0][0] = fmaf(av.x, bv.x, acc[0][0]); acc[0][1] = fmaf(av.x, bv.y, acc[0][1]);
        acc[0][2] = fmaf(av.x, bv.z, acc[0][2]); acc[0][3] = fmaf(av.x, bv.w, acc[0][3]);
        acc[1][0] = fmaf(av.y, bv.x, acc[1][0]); acc[1][1] = fmaf(av.y, bv.y, acc[1][1]);
        acc[1][2] = fmaf(av.y, bv.z, acc[1][2]); acc[1][3] = fmaf(av.y, bv.w, acc[1][3]);
        acc[2][0] = fmaf(av.z, bv.x, acc[2][0]); acc[2][1] = fmaf(av.z, bv.y, acc[2][1]);
        acc[2][2] = fmaf(av.z, bv.z, acc[2][2]); acc[2][3] = fmaf(av.z, bv.w, acc[2][3]);
        acc[3][0] = fmaf(av.w, bv.x, acc[3][0]); acc[3][1] = fmaf(av.w, bv.y, acc[3][1]);
        acc[3][2] = fmaf(av.w, bv.z, acc[3][2]); acc[3][3] = fmaf(av.w, bv.w, acc[3][3]);
    }
    __syncthreads();
#pragma unroll
    for (int r = 0; r < 4; ++r)
#pragma unroll
        for (int c = 0; c < 4; ++c)
            Ct[ib + r][jb + c] = a2s[ib + r] + b2s[jb + c] - 2.f * acc[r][c];
    __syncthreads();

    float* Dp = g_Dd + (size_t)p * NDIAG * T_;
    int kdo = tid >> 6, t = tid & 63;
    for (int kd0 = 0; kd0 < 127; kd0 += 4) {
        int kd = kd0 + kdo;
        if (kd < 127) {
            int ilo = kd > 63 ? kd - 63 : 0;
            int ihi = kd < 63 ? kd : 63;
            int ci = ilo + t;
            if (ci <= ihi) {
                int cj = kd - ci;
                Dp[(size_t)(i0 + ci + j0 + cj) * T_ + (i0 + ci)] = Ct[ci][cj];
            }
        }
    }
}

// ---------------------------------------------------------------------------
// gram body (blocks 60..123 of the fused kernel): 44x44 gram, k-split partials
// ---------------------------------------------------------------------------
__device__ void gram_body(const float* __restrict__ data, int bid, int tid) {
    __shared__ float St[64][49];
    int tx = tid & 15, ty = (tid >> 4) & 15;
    float acc[3][3] = {};
    int k0 = bid * 512;
    for (int sub = 0; sub < 8; ++sub) {
        int kb = k0 + sub * 64;
        __syncthreads();
        for (int f = tid; f < 44 * 16; f += 512) {
            int r = f >> 4, q = f & 15;
            int n = (r / 11) * 16 + (r % 11);
            float4 v = *(const float4*)(data + (size_t)n * 32768 + kb + q * 4);
            St[q * 4 + 0][r] = v.x; St[q * 4 + 1][r] = v.y;
            St[q * 4 + 2][r] = v.z; St[q * 4 + 3][r] = v.w;
        }
        if (tid < 256) { int kk = tid >> 2; int r = 44 + (tid & 3); St[kk][r] = 0.f; }
        __syncthreads();
        if (tid < 256) {
#pragma unroll 8
            for (int kk = 0; kk < 64; ++kk) {
                float a0 = St[kk][ty * 3 + 0], a1 = St[kk][ty * 3 + 1], a2 = St[kk][ty * 3 + 2];
                float b0 = St[kk][tx * 3 + 0], b1 = St[kk][tx * 3 + 1], b2 = St[kk][tx * 3 + 2];
                acc[0][0] = fmaf(a0, b0, acc[0][0]); acc[0][1] = fmaf(a0, b1, acc[0][1]); acc[0][2] = fmaf(a0, b2, acc[0][2]);
                acc[1][0] = fmaf(a1, b0, acc[1][0]); acc[1][1] = fmaf(a1, b1, acc[1][1]); acc[1][2] = fmaf(a1, b2, acc[1][2]);
                acc[2][0] = fmaf(a2, b0, acc[2][0]); acc[2][1] = fmaf(a2, b1, acc[2][1]); acc[2][2] = fmaf(a2, b2, acc[2][2]);
            }
        }
    }
    if (tid < 256) {
        float* gp = g_Gp + bid * 2304;
#pragma unroll
        for (int r = 0; r < 3; ++r)
#pragma unroll
            for (int c = 0; c < 3; ++c)
                gp[(ty * 3 + r) * 48 + (tx * 3 + c)] = acc[r][c];
    }
}

// ---------------------------------------------------------------------------
// Kernel B (fused): blocks [0,60) barrier-free soft-DTW; blocks [60,124) gram.
// DTW: thread i owns row i in registers; neighbor values via shfl.up; the 15
// warp boundaries via a lock-free smem ring (plain store + release counter).
// ---------------------------------------------------------------------------
extern __shared__ unsigned char dynsmem[];

__global__ __launch_bounds__(512) void dtw_gram_kernel(const float* __restrict__ data,
                                                       const int* __restrict__ lens) {
    int bid = blockIdx.x;
    int tid = threadIdx.x;
    if (bid >= NPAIR) { gram_body(data, bid - NPAIR, tid); return; }

    unsigned long long* ring = (unsigned long long*)dynsmem;        // [15][RING_K]
    int* cnts = (int*)(dynsmem + 15 * RING_K * 8);                  // [15]

    int w = bid / 15, jj = bid % 15 + 1;
    int la = lens[w * 16], lb = lens[w * 16 + jj];
    int kmax = la + lb;
    int warp = tid >> 5, lane = tid & 31;
    int i = tid + 1;

    // publish diag-1 boundary values (all BIG for rows >= 32)
    if (lane == 31 && warp < 15) {
        unsigned long long big2 =
            ((unsigned long long)__float_as_uint(BIGV) << 32) | __float_as_uint(BIGV);
        ring[warp * RING_K + 1] = big2;
        cnts[warp] = 1;
    }
    __syncthreads();

    unsigned cons_cnt = 0, cons_dat = 0;
    if (lane == 0 && warp > 0) {
        cons_cnt = (unsigned)__cvta_generic_to_shared(&cnts[warp - 1]);
        cons_dat = (unsigned)__cvta_generic_to_shared(&ring[(warp - 1) * RING_K]);
    }
    unsigned prod_cnt = 0, prod_dat = 0;
    if (lane == 31 && warp < 15) {
        prod_cnt = (unsigned)__cvta_generic_to_shared(&cnts[warp]);
        prod_dat = (unsigned)__cvta_generic_to_shared(&ring[warp * RING_K]);
    }

    const float* Dp = g_Dd + (size_t)bid * NDIAG * T_;
    float cs0 = Dp[0 * T_ + tid];
    float cs1 = Dp[1 * T_ + tid];
    float cs2 = Dp[2 * T_ + tid];

    float p1 = BIGV, p2 = BIGV;       // R at diag k-1 / k-2, row i
    int seen = 1;
    const float c1 = 0.28853900817779268f;    // 1/(GAMMA*ln2)
    const float gln2 = 3.4657359027997265f;   // GAMMA*ln2

    for (int k = 2; k <= kmax; ++k) {
        float n1 = __shfl_up_sync(0xffffffffu, p1, 1);  // R(k-1, i-1)
        float n2 = __shfl_up_sync(0xffffffffu, p2, 1);  // R(k-2, i-1)
        if (lane == 0) {
            if (warp == 0) {
                n1 = BIGV;
                n2 = (k == 2) ? 0.f : BIGV;             // R[0,0]=0 only at diag 0
            } else {
                if (seen < k - 1) {
                    do {
                        asm volatile("ld.acquire.cta.shared.b32 %0, [%1];"
                                     : "=r"(seen) : "r"(cons_cnt));
                    } while (seen < k - 1);
                }
                unsigned long long v;
                asm volatile("ld.shared.b64 %0, [%1];"
                             : "=l"(v) : "r"(cons_dat + (unsigned)(k - 1) * 8u));
                n1 = __uint_as_float((unsigned)v);
                n2 = __uint_as_float((unsigned)(v >> 32));
            }
        }
        float x1 = n2, x2 = n1, x3 = p1;
        float m = fminf(x1, fminf(x2, x3));
        float M = fmaxf(x1, fmaxf(x2, x3));
        float mid = (x1 + x2 + x3) - m - M;
        float S = 1.f + fex2((m - mid) * c1) + fex2((m - M) * c1);
        float r = cs0 + m - gln2 * flg2(S);
        bool act = (i <= la) && (i <= k - 1) && (k - i <= lb);
        r = act ? r : BIGV;
        p2 = p1; p1 = r;

        if (lane == 31 && warp < 15) {
            unsigned long long v =
                ((unsigned long long)__float_as_uint(p2) << 32) | __float_as_uint(p1);
            asm volatile("st.shared.b64 [%0], %1;"
                         :: "r"(prod_dat + (unsigned)k * 8u), "l"(v));
            asm volatile("st.release.cta.shared.b32 [%0], %1;"
                         :: "r"(prod_cnt), "r"(k));
        }
        if (k == kmax && i == la) g_raw[bid] = r;

        int idx = min(k + 1, NDIAG - 1);
        cs0 = cs1; cs1 = cs2;
        cs2 = Dp[(size_t)idx * T_ + tid];
    }
}

// ---------------------------------------------------------------------------
// Kernel C: finishing — parallel reductions (deterministic fixed-order trees)
// ---------------------------------------------------------------------------
__device__ __forceinline__ float warp_sum(float v) {
#pragma unroll
    for (int o = 16; o; o >>= 1) v += __shfl_down_sync(0xffffffffu, v, o);
    return v;
}

__device__ float block_sum(float v, float* part, int tid) {
    float s = warp_sum(v);
    __syncthreads();
    if ((tid & 31) == 0) part[tid >> 5] = s;
    __syncthreads();
    if (tid < 32) {
        float x = (tid < 16) ? part[tid] : 0.f;
        x = warp_sum(x);
        if (tid == 0) part[0] = x;
    }
    __syncthreads();
    return part[0];
}

__global__ __launch_bounds__(512) void final_kernel(const int* __restrict__ lens,
                                                    float* __restrict__ out) {
    __shared__ float sG[44 * 44];
    __shared__ float part[32];
    __shared__ float dist[60];
    __shared__ float sTotal;
    int tid = threadIdx.x;

    for (int t = tid; t < 44 * 44; t += 512) {
        int a = t / 44, b = t % 44;
        float s = 0.f;
#pragma unroll 8
        for (int blk = 0; blk < 64; ++blk) s += g_Gp[blk * 2304 + a * 48 + b];
        sG[t] = s;
    }
    if (tid < 60) {
        int w = tid / 15, jj = tid % 15 + 1;
        dist[tid] = g_raw[tid] / (float)(lens[w * 16] + lens[w * 16 + jj]);
    }
    __syncthreads();

    if (tid == 0) {
        float total = 0.f;
        for (int w = 0; w < 4; ++w) {
            const float* dw = dist + w * 15;
            float mg = 0.f;
            for (int g = 0; g < 5; ++g) mg += dw[g];
            mg *= 0.2f;
            float dk = sqrtf(fabsf(mg));
            float dg[5], dn[10];
            for (int g = 0; g < 5; ++g) dg[g] = dw[g] / dk;
            for (int s = 0; s < 10; ++s) dn[s] = dw[5 + s] / dk;
            float sum = 0.f; int cnt = 0;
            for (int g = 0; g < 5; ++g)
                for (int s = 0; s < 10; ++s) {
                    float v = dg[g] + 1.0f - dn[s];
                    if (v > 0.f) { sum += v; cnt++; }
                }
            float ca = 0.f, cb = 0.f;
            for (int g = 0; g < 5; ++g) ca += dg[g];
            ca *= 0.2f;
            for (int s = 0; s < 5; ++s) cb += dn[s];
            cb *= 0.2f;
            float intra = 0.f;
            for (int g = 0; g < 5; ++g) intra += dg[g] - ca;
            float inter = fmaxf(0.f, 1.0f - fabsf(ca - cb));
            float lv = sum / ((float)cnt + 1.f);
            total += lv + intra * 0.1f + inter * 0.1f;
        }
        sTotal = total * 0.25f;
    }
    __syncthreads();

    const int pwi[9] = {0, 0, 0, 1, 1, 2, 2, 3, 3};
    const int pwj[9] = {1, 2, 3, 2, 3, 1, 3, 1, 2};
    int a = tid / 22, b = tid % 22;
    float mmax = 0.f;
#pragma unroll 1
    for (int pp = 0; pp < 9; ++pp) {
        float l2 = 0.f;
        if (tid < 484) {
            int ra = (a < 11) ? pwi[pp] * 11 + a : pwj[pp] * 11 + (a - 11);
            int rb = (b < 11) ? pwi[pp] * 11 + b : pwj[pp] * 11 + (b - 11);
            l2 = sG[ra * 44 + ra] + sG[rb * 44 + rb] - 2.f * sG[ra * 44 + rb];
        }
        float bw = block_sum(l2, part, tid) * (0.25f / 462.f);
        float kk = 0.f;
        if (tid < 484) {
            float r0 = -l2 / bw * 1.4426950408889634f;   // log2(e)
            kk = fex2(r0) + fex2(r0 * 0.5f) + fex2(r0 * 0.25f)
               + fex2(r0 * 0.125f) + fex2(r0 * 0.0625f);
        }
        float sgn = ((a < 11) == (b < 11)) ? kk : -kk;
        float msum = block_sum(tid < 484 ? sgn : 0.f, part, tid);
        mmax = fmaxf(mmax, msum * (1.f / 121.f));
    }
    if (tid == 0) out[0] = sTotal + mmax * 0.1f;
}

// ---------------------------------------------------------------------------
extern "C" void kernel_launch(void* const* d_in, const int* in_sizes, int n_in,
                              void* d_out, int out_size) {
    const float* data = (const float*)d_in[0];
    const int* lens = (const int*)d_in[1];
    float* out = (float*)d_out;

    cudaFuncSetAttribute(dtw_gram_kernel,
                         cudaFuncAttributeMaxDynamicSharedMemorySize, SMEM_DYN);

    dim3 gA(8, 8, NPAIR);
    cost_kernel<<<gA, 256>>>(data, lens);
    dtw_gram_kernel<<<NPAIR + 64, 512, SMEM_DYN>>>(data, lens);
    final_kernel<<<1, 512>>>(lens, out);
}

// round 4
// speedup vs baseline: 3.0165x; 3.0165x over previous
#include <cuda_runtime.h>

#define T_    512
#define DF    64
#define NPAIR 60
#define NDIAG 1023
#define BIGV  1e10f

static __device__ float g_Dd[(size_t)NPAIR * NDIAG * T_];   // anti-diagonal cost matrices
static __device__ float g_raw[NPAIR];
static __device__ float g_Gp[64 * 48 * 48];                 // gram partials per k-chunk

__device__ __forceinline__ float fex2(float x) { float y; asm("ex2.approx.f32 %0, %1;" : "=f"(y) : "f"(x)); return y; }
__device__ __forceinline__ float flg2(float x) { float y; asm("lg2.approx.f32 %0, %1;" : "=f"(y) : "f"(x)); return y; }

// ---------------------------------------------------------------------------
// Kernel A: squared-Euclidean cost tiles -> anti-diagonal layout g_Dd[p][i+j][i]
// (unchanged from the 335us baseline: measured 59.9us)
// ---------------------------------------------------------------------------
__global__ __launch_bounds__(256) void cost_kernel(const float* __restrict__ data,
                                                   const int* __restrict__ lens) {
    int p = blockIdx.z;
    int w = p / 15, jj = p % 15 + 1;
    int arow = w * 16, brow = arow + jj;
    int la = lens[arow], lb = lens[brow];
    int i0 = blockIdx.y * 64, j0 = blockIdx.x * 64;
    if (i0 >= la || j0 >= lb) return;

    __shared__ float As[64][68];
    __shared__ float Bs[64][68];
    __shared__ float Ct[64][66];
    __shared__ float a2s[64], b2s[64];

    int tid = threadIdx.x;
    const float* Ap = data + (size_t)arow * T_ * DF;
    const float* Bp = data + (size_t)brow * T_ * DF;
#pragma unroll
    for (int it = 0; it < 4; ++it) {
        int f = tid + it * 256;
        int r = f >> 4, q = f & 15;
        float4 va = *(const float4*)(Ap + (size_t)(i0 + r) * DF + q * 4);
        float4 vb = *(const float4*)(Bp + (size_t)(j0 + r) * DF + q * 4);
        As[q * 4 + 0][r] = va.x; As[q * 4 + 1][r] = va.y; As[q * 4 + 2][r] = va.z; As[q * 4 + 3][r] = va.w;
        Bs[q * 4 + 0][r] = vb.x; Bs[q * 4 + 1][r] = vb.y; Bs[q * 4 + 2][r] = vb.z; Bs[q * 4 + 3][r] = vb.w;
    }
    __syncthreads();

    if (tid < 64) {
        float s = 0.f;
#pragma unroll
        for (int k = 0; k < 64; ++k) { float v = As[k][tid]; s = fmaf(v, v, s); }
        a2s[tid] = s;
    } else if (tid < 128) {
        int r = tid - 64; float s = 0.f;
#pragma unroll
        for (int k = 0; k < 64; ++k) { float v = Bs[k][r]; s = fmaf(v, v, s); }
        b2s[r] = s;
    }

    int tx = tid & 15, ty = tid >> 4;
    int ib = ty * 4, jb = tx * 4;
    float acc[4][4] = {};
#pragma unroll 16
    for (int k = 0; k < 64; ++k) {
        float4 av = *(const float4*)&As[k][ib];
        float4 bv = *(const float4*)&Bs[k][jb];
        acc[0][0] = fmaf(av.x, bv.x, acc[0][0]); acc[0][1] = fmaf(av.x, bv.y, acc[0][1]);
        acc[0][2] = fmaf(av.x, bv.z, acc[0][2]); acc[0][3] = fmaf(av.x, bv.w, acc[0][3]);
        acc[1][0] = fmaf(av.y, bv.x, acc[1][0]); acc[1][1] = fmaf(av.y, bv.y, acc[1][1]);
        acc[1][2] = fmaf(av.y, bv.z, acc[1][2]); acc[1][3] = fmaf(av.y, bv.w, acc[1][3]);
        acc[2][0] = fmaf(av.z, bv.x, acc[2][0]); acc[2][1] = fmaf(av.z, bv.y, acc[2][1]);
        acc[2][2] = fmaf(av.z, bv.z, acc[2][2]); acc[2][3] = fmaf(av.z, bv.w, acc[2][3]);
        acc[3][0] = fmaf(av.w, bv.x, acc[3][0]); acc[3][1] = fmaf(av.w, bv.y, acc[3][1]);
        acc[3][2] = fmaf(av.w, bv.z, acc[3][2]); acc[3][3] = fmaf(av.w, bv.w, acc[3][3]);
    }
    __syncthreads();
#pragma unroll
    for (int r = 0; r < 4; ++r)
#pragma unroll
        for (int c = 0; c < 4; ++c)
            Ct[ib + r][jb + c] = a2s[ib + r] + b2s[jb + c] - 2.f * acc[r][c];
    __syncthreads();

    float* Dp = g_Dd + (size_t)p * NDIAG * T_;
    int kdo = tid >> 6, t = tid & 63;
    for (int kd0 = 0; kd0 < 127; kd0 += 4) {
        int kd = kd0 + kdo;
        if (kd < 127) {
            int ilo = kd > 63 ? kd - 63 : 0;
            int ihi = kd < 63 ? kd : 63;
            int ci = ilo + t;
            if (ci <= ihi) {
                int cj = kd - ci;
                Dp[(size_t)(i0 + ci + j0 + cj) * T_ + (i0 + ci)] = Ct[ci][cj];
            }
        }
    }
}

// ---------------------------------------------------------------------------
// gram body (blocks 60..123 of the fused kernel): 44x44 gram, k-split partials
// ---------------------------------------------------------------------------
__device__ void gram_body(const float* __restrict__ data, int bid, int tid) {
    __shared__ float St[64][49];
    int tx = tid & 15, ty = (tid >> 4) & 15;
    float acc[3][3] = {};
    int k0 = bid * 512;
    for (int sub = 0; sub < 8; ++sub) {
        int kb = k0 + sub * 64;
        __syncthreads();
        for (int f = tid; f < 44 * 16; f += 512) {
            int r = f >> 4, q = f & 15;
            int n = (r / 11) * 16 + (r % 11);
            float4 v = *(const float4*)(data + (size_t)n * 32768 + kb + q * 4);
            St[q * 4 + 0][r] = v.x; St[q * 4 + 1][r] = v.y;
            St[q * 4 + 2][r] = v.z; St[q * 4 + 3][r] = v.w;
        }
        if (tid < 256) { int kk = tid >> 2; int r = 44 + (tid & 3); St[kk][r] = 0.f; }
        __syncthreads();
        if (tid < 256) {
#pragma unroll 8
            for (int kk = 0; kk < 64; ++kk) {
                float a0 = St[kk][ty * 3 + 0], a1 = St[kk][ty * 3 + 1], a2 = St[kk][ty * 3 + 2];
                float b0 = St[kk][tx * 3 + 0], b1 = St[kk][tx * 3 + 1], b2 = St[kk][tx * 3 + 2];
                acc[0][0] = fmaf(a0, b0, acc[0][0]); acc[0][1] = fmaf(a0, b1, acc[0][1]); acc[0][2] = fmaf(a0, b2, acc[0][2]);
                acc[1][0] = fmaf(a1, b0, acc[1][0]); acc[1][1] = fmaf(a1, b1, acc[1][1]); acc[1][2] = fmaf(a1, b2, acc[1][2]);
                acc[2][0] = fmaf(a2, b0, acc[2][0]); acc[2][1] = fmaf(a2, b1, acc[2][1]); acc[2][2] = fmaf(a2, b2, acc[2][2]);
            }
        }
    }
    if (tid < 256) {
        float* gp = g_Gp + bid * 2304;
#pragma unroll
        for (int r = 0; r < 3; ++r)
#pragma unroll
            for (int c = 0; c < 3; ++c)
                gp[(ty * 3 + r) * 48 + (tx * 3 + c)] = acc[r][c];
    }
}

// ---------------------------------------------------------------------------
// Kernel B (fused): blocks [0,60): diagonal-blocked soft-DTW, one barrier per
// 32 diagonals; blocks [60,124): gram. Warp w owns rows 32w+1..32w+32 in
// registers. In phase s warp w processes diagonal window [2+(s-w)*32, +31].
// Boundary row values cross warps via a 128-slot smem ring written by lane 31
// and consumed by warp w+1's lane 0 one phase later (ordered by syncthreads).
// ---------------------------------------------------------------------------
__global__ __launch_bounds__(512) void dtw_gram_kernel(const float* __restrict__ data,
                                                       const int* __restrict__ lens) {
    int bid = blockIdx.x;
    int tid = threadIdx.x;
    if (bid >= NPAIR) { gram_body(data, bid - NPAIR, tid); return; }

    __shared__ float bnd[15][128];   // bnd[w][k&127] = R(k, row 32w+32)

    int w = bid / 15, jj = bid % 15 + 1;
    int la = lens[w * 16], lb = lens[w * 16 + jj];
    int kmax = la + lb;
    int warp = tid >> 5, lane = tid & 31;
    int i = tid + 1;                            // this thread's DP row

    // pre-init slot k=1 (read by every warp's first window step k=2)
    if (tid < 15) bnd[tid][1] = BIGV;
    __syncthreads();

    const float* Dp = g_Dd + (size_t)bid * NDIAG * T_;
    const float c1 = 0.28853900817779268f;     // 1/(GAMMA*ln2)
    const float gln2 = 3.4657359027997265f;    // GAMMA*ln2

    float p1 = BIGV;                            // R(k-1, i)
    float n1p = (tid == 0) ? 0.f : BIGV;        // previous n1 -> R(k-2, i-1)

    int nblk = (kmax - 1 + 31) >> 5;            // ceil((kmax-1)/32)
    int S = nblk + 15;

    for (int s = 0; s < S; ++s) {
        int t = s - warp;
        if (t >= 0 && t < nblk) {
            int k0 = 2 + t * 32;
            float cs[32];
#pragma unroll
            for (int d = 0; d < 32; ++d) {
                int row = min(k0 - 2 + d, NDIAG - 1);
                cs[d] = Dp[(size_t)row * T_ + tid];
            }
#pragma unroll
            for (int d = 0; d < 32; ++d) {
                int k = k0 + d;
                float n1 = __shfl_up_sync(0xffffffffu, p1, 1);   // R(k-1, i-1)
                if (lane == 0)
                    n1 = (warp == 0) ? BIGV : bnd[warp - 1][(k - 1) & 127];
                float n2 = n1p;                                   // R(k-2, i-1)
                float m = fminf(n2, fminf(n1, p1));
                float M = fmaxf(n2, fmaxf(n1, p1));
                float mid = (n2 + n1 + p1) - m - M;
                float S2 = 1.f + fex2((m - mid) * c1) + fex2((m - M) * c1);
                float r = cs[d] + m - gln2 * flg2(S2);
                bool act = (i <= la) && (k - i >= 1) && (k - i <= lb);
                r = act ? r : BIGV;
                n1p = n1;
                p1 = r;
                if (lane == 31 && warp < 15) bnd[warp][k & 127] = r;
                if (k == kmax && i == la) g_raw[bid] = r;
            }
        }
        __syncthreads();
    }
}

// ---------------------------------------------------------------------------
// Kernel C: finishing — parallel reductions (deterministic fixed-order trees)
// ---------------------------------------------------------------------------
__device__ __forceinline__ float warp_sum(float v) {
#pragma unroll
    for (int o = 16; o; o >>= 1) v += __shfl_down_sync(0xffffffffu, v, o);
    return v;
}

__device__ float block_sum(float v, float* part, int tid) {
    float s = warp_sum(v);
    __syncthreads();
    if ((tid & 31) == 0) part[tid >> 5] = s;
    __syncthreads();
    if (tid < 32) {
        float x = (tid < 16) ? part[tid] : 0.f;
        x = warp_sum(x);
        if (tid == 0) part[0] = x;
    }
    __syncthreads();
    return part[0];
}

__global__ __launch_bounds__(512) void final_kernel(const int* __restrict__ lens,
                                                    float* __restrict__ out) {
    __shared__ float sG[44 * 44];
    __shared__ float part[32];
    __shared__ float dist[60];
    __shared__ float sTotal;
    int tid = threadIdx.x;

    for (int t = tid; t < 44 * 44; t += 512) {
        int a = t / 44, b = t % 44;
        float s = 0.f;
#pragma unroll 8
        for (int blk = 0; blk < 64; ++blk) s += g_Gp[blk * 2304 + a * 48 + b];
        sG[t] = s;
    }
    if (tid < 60) {
        int w = tid / 15, jj = tid % 15 + 1;
        dist[tid] = g_raw[tid] / (float)(lens[w * 16] + lens[w * 16 + jj]);
    }
    __syncthreads();

    if (tid == 0) {
        float total = 0.f;
        for (int w = 0; w < 4; ++w) {
            const float* dw = dist + w * 15;
            float mg = 0.f;
            for (int g = 0; g < 5; ++g) mg += dw[g];
            mg *= 0.2f;
            float dk = sqrtf(fabsf(mg));
            float dg[5], dn[10];
            for (int g = 0; g < 5; ++g) dg[g] = dw[g] / dk;
            for (int s = 0; s < 10; ++s) dn[s] = dw[5 + s] / dk;
            float sum = 0.f; int cnt = 0;
            for (int g = 0; g < 5; ++g)
                for (int s = 0; s < 10; ++s) {
                    float v = dg[g] + 1.0f - dn[s];
                    if (v > 0.f) { sum += v; cnt++; }
                }
            float ca = 0.f, cb = 0.f;
            for (int g = 0; g < 5; ++g) ca += dg[g];
            ca *= 0.2f;
            for (int s = 0; s < 5; ++s) cb += dn[s];
            cb *= 0.2f;
            float intra = 0.f;
            for (int g = 0; g < 5; ++g) intra += dg[g] - ca;
            float inter = fmaxf(0.f, 1.0f - fabsf(ca - cb));
            float lv = sum / ((float)cnt + 1.f);
            total += lv + intra * 0.1f + inter * 0.1f;
        }
        sTotal = total * 0.25f;
    }
    __syncthreads();

    const int pwi[9] = {0, 0, 0, 1, 1, 2, 2, 3, 3};
    const int pwj[9] = {1, 2, 3, 2, 3, 1, 3, 1, 2};
    int a = tid / 22, b = tid % 22;
    float mmax = 0.f;
#pragma unroll 1
    for (int pp = 0; pp < 9; ++pp) {
        float l2 = 0.f;
        if (tid < 484) {
            int ra = (a < 11) ? pwi[pp] * 11 + a : pwj[pp] * 11 + (a - 11);
            int rb = (b < 11) ? pwi[pp] * 11 + b : pwj[pp] * 11 + (b - 11);
            l2 = sG[ra * 44 + ra] + sG[rb * 44 + rb] - 2.f * sG[ra * 44 + rb];
        }
        float bw = block_sum(l2, part, tid) * (0.25f / 462.f);
        float kk = 0.f;
        if (tid < 484) {
            float r0 = -l2 / bw * 1.4426950408889634f;   // log2(e)
            kk = fex2(r0) + fex2(r0 * 0.5f) + fex2(r0 * 0.25f)
               + fex2(r0 * 0.125f) + fex2(r0 * 0.0625f);
        }
        float sgn = ((a < 11) == (b < 11)) ? kk : -kk;
        float msum = block_sum(tid < 484 ? sgn : 0.f, part, tid);
        mmax = fmaxf(mmax, msum * (1.f / 121.f));
    }
    if (tid == 0) out[0] = sTotal + mmax * 0.1f;
}

// ---------------------------------------------------------------------------
extern "C" void kernel_launch(void* const* d_in, const int* in_sizes, int n_in,
                              void* d_out, int out_size) {
    const float* data = (const float*)d_in[0];
    const int* lens = (const int*)d_in[1];
    float* out = (float*)d_out;

    dim3 gA(8, 8, NPAIR);
    cost_kernel<<<gA, 256>>>(data, lens);
    dtw_gram_kernel<<<NPAIR + 64, 512>>>(data, lens);
    final_kernel<<<1, 512>>>(lens, out);
}

// round 5
// speedup vs baseline: 3.2695x; 1.0839x over previous
#include <cuda_runtime.h>

#define T_    512
#define DF    64
#define NPAIR 60
#define NDIAG 1023
#define BIGV  1e10f

static __device__ float g_Dd[(size_t)NPAIR * NDIAG * T_];   // anti-diagonal cost matrices
static __device__ float g_raw[NPAIR];
static __device__ float g_Gp[64 * 48 * 48];                 // gram partials per k-chunk

__device__ __forceinline__ float fex2(float x) { float y; asm("ex2.approx.f32 %0, %1;" : "=f"(y) : "f"(x)); return y; }
__device__ __forceinline__ float flg2(float x) { float y; asm("lg2.approx.f32 %0, %1;" : "=f"(y) : "f"(x)); return y; }

// packed f32x2 FMA (SASS FFMA2; only reachable via PTX fma.rn.f32x2)
__device__ __forceinline__ void ffma2(float2& d, float2 a, float2 b) {
    asm("fma.rn.f32x2 %0, %1, %2, %0;"
        : "+l"(*reinterpret_cast<unsigned long long*>(&d))
        : "l"(*reinterpret_cast<unsigned long long*>(&a)),
          "l"(*reinterpret_cast<unsigned long long*>(&b)));
}

// dynamic smem layout for cost_kernel (Ct aliases As2: all As2 reads precede Ct writes)
#define CK_AS2_BYTES (64 * 66 * 8)                    // float2 [64][66]
#define CK_BS_OFF    CK_AS2_BYTES
#define CK_BS_BYTES  (64 * 68 * 4)                    // float [64][68]
#define CK_A2_OFF    (CK_BS_OFF + CK_BS_BYTES)
#define CK_B2_OFF    (CK_A2_OFF + 256)
#define CK_SMEM      (CK_B2_OFF + 256)                // 51712 B

// ---------------------------------------------------------------------------
// Kernel A: squared-Euclidean cost tiles -> anti-diagonal layout g_Dd[p][i+j][i]
// A values stored duplicated (a,a) so the GEMM runs on FFMA2 without packing.
// ---------------------------------------------------------------------------
__global__ __launch_bounds__(256) void cost_kernel(const float* __restrict__ data,
                                                   const int* __restrict__ lens) {
    extern __shared__ unsigned char dynsm[];
    float2 (*As2)[66] = reinterpret_cast<float2(*)[66]>(dynsm);
    float  (*Bs)[68]  = reinterpret_cast<float(*)[68]>(dynsm + CK_BS_OFF);
    float  (*Ct)[66]  = reinterpret_cast<float(*)[66]>(dynsm);   // alias As2
    float* a2s = (float*)(dynsm + CK_A2_OFF);
    float* b2s = (float*)(dynsm + CK_B2_OFF);

    int p = blockIdx.z;
    int w = p / 15, jj = p % 15 + 1;
    int arow = w * 16, brow = arow + jj;
    int la = lens[arow], lb = lens[brow];
    int i0 = blockIdx.y * 64, j0 = blockIdx.x * 64;
    if (i0 >= la || j0 >= lb) return;

    int tid = threadIdx.x;
    const float* Ap = data + (size_t)arow * T_ * DF;
    const float* Bp = data + (size_t)brow * T_ * DF;
#pragma unroll
    for (int it = 0; it < 4; ++it) {
        int f = tid + it * 256;
        int r = f >> 4, q = f & 15;
        float4 va = *(const float4*)(Ap + (size_t)(i0 + r) * DF + q * 4);
        float4 vb = *(const float4*)(Bp + (size_t)(j0 + r) * DF + q * 4);
        As2[q * 4 + 0][r] = make_float2(va.x, va.x);
        As2[q * 4 + 1][r] = make_float2(va.y, va.y);
        As2[q * 4 + 2][r] = make_float2(va.z, va.z);
        As2[q * 4 + 3][r] = make_float2(va.w, va.w);
        Bs[q * 4 + 0][r] = vb.x; Bs[q * 4 + 1][r] = vb.y;
        Bs[q * 4 + 2][r] = vb.z; Bs[q * 4 + 3][r] = vb.w;
    }
    __syncthreads();

    if (tid < 64) {
        float s = 0.f;
#pragma unroll
        for (int k = 0; k < 64; ++k) { float v = As2[k][tid].x; s = fmaf(v, v, s); }
        a2s[tid] = s;
    } else if (tid < 128) {
        int r = tid - 64; float s = 0.f;
#pragma unroll
        for (int k = 0; k < 64; ++k) { float v = Bs[k][r]; s = fmaf(v, v, s); }
        b2s[r] = s;
    }

    int tx = tid & 15, ty = tid >> 4;
    int ib = ty * 4, jb = tx * 4;
    float2 acc2[4][2] = {};
#pragma unroll 16
    for (int k = 0; k < 64; ++k) {
        float2 a0 = As2[k][ib + 0], a1 = As2[k][ib + 1];
        float2 a2 = As2[k][ib + 2], a3 = As2[k][ib + 3];
        float4 bv = *(const float4*)&Bs[k][jb];
        float2 b01 = make_float2(bv.x, bv.y), b23 = make_float2(bv.z, bv.w);
        ffma2(acc2[0][0], a0, b01); ffma2(acc2[0][1], a0, b23);
        ffma2(acc2[1][0], a1, b01); ffma2(acc2[1][1], a1, b23);
        ffma2(acc2[2][0], a2, b01); ffma2(acc2[2][1], a2, b23);
        ffma2(acc2[3][0], a3, b01); ffma2(acc2[3][1], a3, b23);
    }
    __syncthreads();   // all As2/Bs reads done; a2s/b2s visible; Ct may overwrite As2
#pragma unroll
    for (int r = 0; r < 4; ++r) {
        float a2v = a2s[ib + r];
        Ct[ib + r][jb + 0] = a2v + b2s[jb + 0] - 2.f * acc2[r][0].x;
        Ct[ib + r][jb + 1] = a2v + b2s[jb + 1] - 2.f * acc2[r][0].y;
        Ct[ib + r][jb + 2] = a2v + b2s[jb + 2] - 2.f * acc2[r][1].x;
        Ct[ib + r][jb + 3] = a2v + b2s[jb + 3] - 2.f * acc2[r][1].y;
    }
    __syncthreads();

    float* Dp = g_Dd + (size_t)p * NDIAG * T_;
    int kdo = tid >> 6, t = tid & 63;
    for (int kd0 = 0; kd0 < 127; kd0 += 4) {
        int kd = kd0 + kdo;
        if (kd < 127) {
            int ilo = kd > 63 ? kd - 63 : 0;
            int ihi = kd < 63 ? kd : 63;
            int ci = ilo + t;
            if (ci <= ihi) {
                int cj = kd - ci;
                Dp[(size_t)(i0 + ci + j0 + cj) * T_ + (i0 + ci)] = Ct[ci][cj];
            }
        }
    }
}

// ---------------------------------------------------------------------------
// gram body (blocks 60..123 of the fused kernel): 44x44 gram, k-split partials
// ---------------------------------------------------------------------------
__device__ void gram_body(const float* __restrict__ data, int bid, int tid) {
    __shared__ float St[64][49];
    int tx = tid & 15, ty = (tid >> 4) & 15;
    float acc[3][3] = {};
    int k0 = bid * 512;
    for (int sub = 0; sub < 8; ++sub) {
        int kb = k0 + sub * 64;
        __syncthreads();
        for (int f = tid; f < 44 * 16; f += 512) {
            int r = f >> 4, q = f & 15;
            int n = (r / 11) * 16 + (r % 11);
            float4 v = *(const float4*)(data + (size_t)n * 32768 + kb + q * 4);
            St[q * 4 + 0][r] = v.x; St[q * 4 + 1][r] = v.y;
            St[q * 4 + 2][r] = v.z; St[q * 4 + 3][r] = v.w;
        }
        if (tid < 256) { int kk = tid >> 2; int r = 44 + (tid & 3); St[kk][r] = 0.f; }
        __syncthreads();
        if (tid < 256) {
#pragma unroll 8
            for (int kk = 0; kk < 64; ++kk) {
                float a0 = St[kk][ty * 3 + 0], a1 = St[kk][ty * 3 + 1], a2 = St[kk][ty * 3 + 2];
                float b0 = St[kk][tx * 3 + 0], b1 = St[kk][tx * 3 + 1], b2 = St[kk][tx * 3 + 2];
                acc[0][0] = fmaf(a0, b0, acc[0][0]); acc[0][1] = fmaf(a0, b1, acc[0][1]); acc[0][2] = fmaf(a0, b2, acc[0][2]);
                acc[1][0] = fmaf(a1, b0, acc[1][0]); acc[1][1] = fmaf(a1, b1, acc[1][1]); acc[1][2] = fmaf(a1, b2, acc[1][2]);
                acc[2][0] = fmaf(a2, b0, acc[2][0]); acc[2][1] = fmaf(a2, b1, acc[2][1]); acc[2][2] = fmaf(a2, b2, acc[2][2]);
            }
        }
    }
    if (tid < 256) {
        float* gp = g_Gp + bid * 2304;
#pragma unroll
        for (int r = 0; r < 3; ++r)
#pragma unroll
            for (int c = 0; c < 3; ++c)
                gp[(ty * 3 + r) * 48 + (tx * 3 + c)] = acc[r][c];
    }
}

// ---------------------------------------------------------------------------
// Kernel B (fused): blocks [0,60): diagonal-blocked soft-DTW with per-warp
// window skipping; blocks [60,124): gram.
// ---------------------------------------------------------------------------
__global__ __launch_bounds__(512) void dtw_gram_kernel(const float* __restrict__ data,
                                                       const int* __restrict__ lens) {
    int bid = blockIdx.x;
    int tid = threadIdx.x;
    if (bid >= NPAIR) { gram_body(data, bid - NPAIR, tid); return; }

    __shared__ float bnd[15][128];   // bnd[w][k&127] = R(k, row 32w+32)

    int w = bid / 15, jj = bid % 15 + 1;
    int la = lens[w * 16], lb = lens[w * 16 + jj];
    int kmax = la + lb;
    int warp = tid >> 5, lane = tid & 31;
    int i = tid + 1;                              // this thread's DP row

    const float* Dp = g_Dd + (size_t)bid * NDIAG * T_;
    const float c1 = 0.28853900817779268f;       // 1/(GAMMA*ln2)
    const float gln2 = 3.4657359027997265f;      // GAMMA*ln2

    float p1 = BIGV;                              // R(k-1, i)
    float n1p = (tid == 0) ? 0.f : BIGV;          // previous n1 -> R(k-2, i-1)

    int nblk = (kmax - 1 + 31) >> 5;              // windows covering diag 2..kmax
    int nph = nblk + 15;
    bool rowact = (32 * warp + 1) <= la;          // warp has any active rows
    int thi = min(nblk - 1, (32 * warp + 30 + lb) >> 5);   // trailing j-bound

    for (int s = 0; s < nph; ++s) {
        int t = s - warp;
        if (rowact && t >= warp && t <= thi) {    // skip leading t<warp + trailing
            int k0 = 2 + t * 32;
            float cs[32];
#pragma unroll
            for (int d = 0; d < 32; ++d)
                cs[d] = Dp[(size_t)min(k0 - 2 + d, NDIAG - 1) * T_ + tid];

            bool full = (32 * warp + 32 <= la) && (k0 >= 32 * warp + 33)
                     && (k0 + 31 <= 32 * warp + 1 + lb);
            if (full) {
#pragma unroll
                for (int d = 0; d < 32; ++d) {
                    int k = k0 + d;
                    float n1 = __shfl_up_sync(0xffffffffu, p1, 1);
                    if (lane == 0)
                        n1 = (warp == 0) ? BIGV : bnd[warp - 1][(k - 1) & 127];
                    float pmn = fminf(n1, n1p);
                    float pmx = fmaxf(n1, n1p);
                    float psm = n1 + n1p;
                    n1p = n1;
                    float m = fminf(pmn, p1);
                    float M = fmaxf(pmx, p1);
                    float mid = (psm + p1) - m - M;
                    float S2 = 1.f + fex2((m - mid) * c1) + fex2((m - M) * c1);
                    float r = cs[d] + m - gln2 * flg2(S2);
                    p1 = r;
                    if (lane == 31 && warp < 15) bnd[warp][k & 127] = r;
                }
            } else {
                bool iact = (i <= la);
#pragma unroll
                for (int d = 0; d < 32; ++d) {
                    int k = k0 + d;
                    float n1 = __shfl_up_sync(0xffffffffu, p1, 1);
                    if (lane == 0)
                        n1 = (warp == 0) ? BIGV : bnd[warp - 1][(k - 1) & 127];
                    float pmn = fminf(n1, n1p);
                    float pmx = fmaxf(n1, n1p);
                    float psm = n1 + n1p;
                    n1p = n1;
                    float m = fminf(pmn, p1);
                    float M = fmaxf(pmx, p1);
                    float mid = (psm + p1) - m - M;
                    float S2 = 1.f + fex2((m - mid) * c1) + fex2((m - M) * c1);
                    float r = cs[d] + m - gln2 * flg2(S2);
                    bool act = iact && (k > i) && (k <= i + lb);
                    r = act ? r : BIGV;
                    p1 = r;
                    if (lane == 31 && warp < 15) bnd[warp][k & 127] = r;
                    if (k == kmax && i == la) g_raw[bid] = r;
                }
            }
        }
        __syncthreads();
    }
}

// ---------------------------------------------------------------------------
// Kernel C: finishing — parallel reductions (deterministic fixed-order trees)
// ---------------------------------------------------------------------------
__device__ __forceinline__ float warp_sum(float v) {
#pragma unroll
    for (int o = 16; o; o >>= 1) v += __shfl_down_sync(0xffffffffu, v, o);
    return v;
}

__device__ float block_sum(float v, float* part, int tid) {
    float s = warp_sum(v);
    __syncthreads();
    if ((tid & 31) == 0) part[tid >> 5] = s;
    __syncthreads();
    if (tid < 32) {
        float x = (tid < 16) ? part[tid] : 0.f;
        x = warp_sum(x);
        if (tid == 0) part[0] = x;
    }
    __syncthreads();
    return part[0];
}

__global__ __launch_bounds__(512) void final_kernel(const int* __restrict__ lens,
                                                    float* __restrict__ out) {
    __shared__ float sG[44 * 44];
    __shared__ float part[32];
    __shared__ float dist[60];
    __shared__ float sTotal;
    int tid = threadIdx.x;

    for (int t = tid; t < 44 * 44; t += 512) {
        int a = t / 44, b = t % 44;
        float s = 0.f;
#pragma unroll 8
        for (int blk = 0; blk < 64; ++blk) s += g_Gp[blk * 2304 + a * 48 + b];
        sG[t] = s;
    }
    if (tid < 60) {
        int w = tid / 15, jj = tid % 15 + 1;
        dist[tid] = g_raw[tid] / (float)(lens[w * 16] + lens[w * 16 + jj]);
    }
    __syncthreads();

    if (tid == 0) {
        float total = 0.f;
        for (int w = 0; w < 4; ++w) {
            const float* dw = dist + w * 15;
            float mg = 0.f;
            for (int g = 0; g < 5; ++g) mg += dw[g];
            mg *= 0.2f;
            float dk = sqrtf(fabsf(mg));
            float dg[5], dn[10];
            for (int g = 0; g < 5; ++g) dg[g] = dw[g] / dk;
            for (int s = 0; s < 10; ++s) dn[s] = dw[5 + s] / dk;
            float sum = 0.f; int cnt = 0;
            for (int g = 0; g < 5; ++g)
                for (int s = 0; s < 10; ++s) {
                    float v = dg[g] + 1.0f - dn[s];
                    if (v > 0.f) { sum += v; cnt++; }
                }
            float ca = 0.f, cb = 0.f;
            for (int g = 0; g < 5; ++g) ca += dg[g];
            ca *= 0.2f;
            for (int s = 0; s < 5; ++s) cb += dn[s];
            cb *= 0.2f;
            float intra = 0.f;
            for (int g = 0; g < 5; ++g) intra += dg[g] - ca;
            float inter = fmaxf(0.f, 1.0f - fabsf(ca - cb));
            float lv = sum / ((float)cnt + 1.f);
            total += lv + intra * 0.1f + inter * 0.1f;
        }
        sTotal = total * 0.25f;
    }
    __syncthreads();

    const int pwi[9] = {0, 0, 0, 1, 1, 2, 2, 3, 3};
    const int pwj[9] = {1, 2, 3, 2, 3, 1, 3, 1, 2};
    int a = tid / 22, b = tid % 22;
    float mmax = 0.f;
#pragma unroll 1
    for (int pp = 0; pp < 9; ++pp) {
        float l2 = 0.f;
        if (tid < 484) {
            int ra = (a < 11) ? pwi[pp] * 11 + a : pwj[pp] * 11 + (a - 11);
            int rb = (b < 11) ? pwi[pp] * 11 + b : pwj[pp] * 11 + (b - 11);
            l2 = sG[ra * 44 + ra] + sG[rb * 44 + rb] - 2.f * sG[ra * 44 + rb];
        }
        float bw = block_sum(l2, part, tid) * (0.25f / 462.f);
        float kk = 0.f;
        if (tid < 484) {
            float r0 = -l2 / bw * 1.4426950408889634f;   // log2(e)
            kk = fex2(r0) + fex2(r0 * 0.5f) + fex2(r0 * 0.25f)
               + fex2(r0 * 0.125f) + fex2(r0 * 0.0625f);
        }
        float sgn = ((a < 11) == (b < 11)) ? kk : -kk;
        float msum = block_sum(tid < 484 ? sgn : 0.f, part, tid);
        mmax = fmaxf(mmax, msum * (1.f / 121.f));
    }
    if (tid == 0) out[0] = sTotal + mmax * 0.1f;
}

// ---------------------------------------------------------------------------
extern "C" void kernel_launch(void* const* d_in, const int* in_sizes, int n_in,
                              void* d_out, int out_size) {
    const float* data = (const float*)d_in[0];
    const int* lens = (const int*)d_in[1];
    float* out = (float*)d_out;

    cudaFuncSetAttribute(cost_kernel,
                         cudaFuncAttributeMaxDynamicSharedMemorySize, CK_SMEM);

    dim3 gA(8, 8, NPAIR);
    cost_kernel<<<gA, 256, CK_SMEM>>>(data, lens);
    dtw_gram_kernel<<<NPAIR + 64, 512>>>(data, lens);
    final_kernel<<<1, 512>>>(lens, out);
}